// round 4
// baseline (speedup 1.0000x reference)
#include <cuda_runtime.h>
#include <math_constants.h>

// Sampler: B=256 rows, V=128000 vocab.
// inputs: logits [B,V] f32, temperatures [B] f32, uniform_noise [B,V] f32
// output: [tokens (B floats)] ++ [probs (B*V floats)]

#define NT 512
#define BB 256
#define VV 128000
#define NVEC (VV / 4)          // 32000 float4 chunks per row
#define L2E 1.4426950408889634f

__global__ void __launch_bounds__(NT)
sampler_kernel(const float* __restrict__ logits,
               const float* __restrict__ temps,
               const float* __restrict__ noise,
               float* __restrict__ out)
{
    const int b    = blockIdx.x;
    const int tid  = threadIdx.x;
    const int lane = tid & 31;
    const int wid  = tid >> 5;           // 0..15

    const float t      = temps[b];
    const float safe_t = (t == 0.0f) ? 1.0f : t;
    const float inv_t  = 1.0f / safe_t;

    const float4* __restrict__ lrow = (const float4*)(logits + (size_t)b * VV);
    const float4* __restrict__ nrow = (const float4*)(noise  + (size_t)b * VV);
    float4* __restrict__ prow       = (float4*)(out + BB + (size_t)b * VV);

    // greedy argmax over raw logits; sample argmax over sc+g; online exp-sum
    float gv = -CUDART_INF_F; int gi = 0;
    float sv = -CUDART_INF_F; int si = 0;
    float m  = -CUDART_INF_F;   // per-thread running max of sc
    float s  = 0.0f;            // per-thread sum of exp(sc - m)

    for (int j = tid; j < NVEC; j += NT) {
        const float4 l4 = lrow[j];
        const float4 n4 = __ldcs(nrow + j);     // streamed, evict-first
        const float lv[4] = {l4.x, l4.y, l4.z, l4.w};
        const float nv[4] = {n4.x, n4.y, n4.z, n4.w};
        #pragma unroll
        for (int k = 0; k < 4; k++) {
            const int idx = 4 * j + k;
            const float l = lv[k];
            if (l > gv) { gv = l; gi = idx; }           // ascending idx -> lowest tie idx
            const float sc = l * inv_t;
            // Gumbel: first log must be accurate (u -> 1 tail); second can be fast
            const float y = -logf(nv[k]);               // accurate
            const float g = -__logf(y);                 // MUFU-based, abs-err ~1e-7 ok
            const float z = sc + g;
            if (z > sv) { sv = z; si = idx; }
            // online exp-sum (branch rarely taken after warmup)
            if (sc > m) {
                s = s * __expf(m - sc) + 1.0f;
                m = sc;
            } else {
                s += __expf(sc - m);
            }
        }
    }

    // ---- Phase A: block argmax reductions ----
    __shared__ float sh_gv[16]; __shared__ int sh_gi[16];
    __shared__ float sh_sv[16]; __shared__ int sh_si[16];
    __shared__ float sh_sum[16];
    __shared__ float fin_M, fin_c;

    #pragma unroll
    for (int off = 16; off; off >>= 1) {
        float v = __shfl_xor_sync(0xffffffffu, gv, off);
        int   i = __shfl_xor_sync(0xffffffffu, gi, off);
        if (v > gv || (v == gv && i < gi)) { gv = v; gi = i; }
        float v2 = __shfl_xor_sync(0xffffffffu, sv, off);
        int   i2 = __shfl_xor_sync(0xffffffffu, si, off);
        if (v2 > sv || (v2 == sv && i2 < si)) { sv = v2; si = i2; }
    }
    if (lane == 0) { sh_gv[wid] = gv; sh_gi[wid] = gi; sh_sv[wid] = sv; sh_si[wid] = si; }
    __syncthreads();

    if (wid == 0 && lane < 16) {
        float v = sh_gv[lane]; int i = sh_gi[lane];
        float v2 = sh_sv[lane]; int i2 = sh_si[lane];
        #pragma unroll
        for (int off = 8; off; off >>= 1) {
            float wv = __shfl_xor_sync(0xffffu, v, off);
            int   wi = __shfl_xor_sync(0xffffu, i, off);
            if (wv > v || (wv == v && wi < i)) { v = wv; i = wi; }
            float wv2 = __shfl_xor_sync(0xffffu, v2, off);
            int   wi2 = __shfl_xor_sync(0xffffu, i2, off);
            if (wv2 > v2 || (wv2 == v2 && wi2 < i2)) { v2 = wv2; i2 = wi2; }
        }
        if (lane == 0) {
            // row max of sc is exactly fl(max_l * inv_t) (monotone rounding)
            fin_M = v * inv_t;
            const int tok = (t == 0.0f) ? i : i2;
            out[b] = (float)tok;
        }
    }
    __syncthreads();

    // ---- Phase B: exp-sum reduction rebased to the global max ----
    const float M = fin_M;
    float contrib = s * __expf(m - M);     // m <= M; exp(-inf)=0 for idle threads
    #pragma unroll
    for (int off = 16; off; off >>= 1)
        contrib += __shfl_xor_sync(0xffffffffu, contrib, off);
    if (lane == 0) sh_sum[wid] = contrib;
    __syncthreads();
    if (wid == 0 && lane < 16) {
        float c = sh_sum[lane];
        #pragma unroll
        for (int off = 8; off; off >>= 1)
            c += __shfl_xor_sync(0xffffu, c, off);
        if (lane == 0)
            fin_c = fmaf(-M, L2E, log2f(1.0f / c));  // fold norm into exponent
    }
    __syncthreads();

    // ---- Pass 2: probs = exp2(l*a + c), logits reread is L2-hot ----
    const float a = inv_t * L2E;
    const float c = fin_c;
    for (int j = tid; j < NVEC; j += NT) {
        const float4 l4 = lrow[j];
        float4 p;
        p.x = exp2f(fmaf(l4.x, a, c));
        p.y = exp2f(fmaf(l4.y, a, c));
        p.z = exp2f(fmaf(l4.z, a, c));
        p.w = exp2f(fmaf(l4.w, a, c));
        __stcs(prow + j, p);               // streaming store, don't pollute L2
    }
}

extern "C" void kernel_launch(void* const* d_in, const int* in_sizes, int n_in,
                              void* d_out, int out_size) {
    const float* logits = (const float*)d_in[0];
    const float* temps  = (const float*)d_in[1];
    const float* noise  = (const float*)d_in[2];
    float* out = (float*)d_out;
    sampler_kernel<<<BB, NT>>>(logits, temps, noise, out);
}

// round 5
// speedup vs baseline: 1.5124x; 1.5124x over previous
#include <cuda_runtime.h>
#include <math_constants.h>

// Sampler: B=256 rows, V=128000 vocab.
// inputs: logits [B,V] f32, temperatures [B] f32, uniform_noise [B,V] f32
// output: [tokens (B floats)] ++ [probs (B*V floats)]

#define NT 1024
#define BB 256
#define VV 128000
#define NVEC (VV / 4)                 // 32000 float4 chunks per row
#define L2E 1.4426950408889634f
#define LN2 0.6931471805599453f

__device__ __forceinline__ float lg2a(float x) {
    float r; asm("lg2.approx.f32 %0, %1;" : "=f"(r) : "f"(x)); return r;
}
__device__ __forceinline__ float ex2a(float x) {
    float r; asm("ex2.approx.f32 %0, %1;" : "=f"(r) : "f"(x)); return r;
}

__global__ void __launch_bounds__(NT)
sampler_kernel(const float* __restrict__ logits,
               const float* __restrict__ temps,
               const float* __restrict__ noise,
               float* __restrict__ out)
{
    const int b    = blockIdx.x;
    const int tid  = threadIdx.x;
    const int lane = tid & 31;
    const int wid  = tid >> 5;            // 0..31

    const float t      = temps[b];
    const float safe_t = (t == 0.0f) ? 1.0f : t;
    const float inv_t  = 1.0f / safe_t;

    const float4* __restrict__ lrow = (const float4*)(logits + (size_t)b * VV);
    const float4* __restrict__ nrow = (const float4*)(noise  + (size_t)b * VV);
    float4* __restrict__ prow       = (float4*)(out + BB + (size_t)b * VV);

    // ---- pass 1: greedy argmax + Gumbel argmax (no softmax sum here) ----
    float gv = -CUDART_INF_F; int gi = 0;
    float sv = -CUDART_INF_F; int si = 0;

    for (int j = tid; j < NVEC; j += NT) {
        const float4 l4 = lrow[j];
        const float4 n4 = __ldcs(nrow + j);           // single-use: stream
        const float lv[4] = {l4.x, l4.y, l4.z, l4.w};
        const float nv[4] = {n4.x, n4.y, n4.z, n4.w};
        #pragma unroll
        for (int k = 0; k < 4; k++) {
            const int idx = 4 * j + k;
            const float l = lv[k];
            const float u = nv[k];
            if (l > gv) { gv = l; gi = idx; }         // ascending idx => lowest tie idx
            // y = -log(u): fast LG2, exact series fixup for the u->1 tail
            float y = (-LN2) * lg2a(u);
            const float d = 1.0f - u;
            if (u > 0.99f)
                y = d * fmaf(d, fmaf(d, 0.33333333f, 0.5f), 1.0f);
            // z = l/t + g,  g = -log(y)
            const float z = fmaf(lg2a(y), -LN2, l * inv_t);
            if (z > sv) { sv = z; si = idx; }
        }
    }

    // ---- block argmax reductions ----
    __shared__ float sh_gv[32]; __shared__ int sh_gi[32];
    __shared__ float sh_sv[32]; __shared__ int sh_si[32];
    __shared__ float sh_sum[32];
    __shared__ float fin_M, fin_c;

    #pragma unroll
    for (int off = 16; off; off >>= 1) {
        float v = __shfl_xor_sync(0xffffffffu, gv, off);
        int   i = __shfl_xor_sync(0xffffffffu, gi, off);
        if (v > gv || (v == gv && i < gi)) { gv = v; gi = i; }
        float v2 = __shfl_xor_sync(0xffffffffu, sv, off);
        int   i2 = __shfl_xor_sync(0xffffffffu, si, off);
        if (v2 > sv || (v2 == sv && i2 < si)) { sv = v2; si = i2; }
    }
    if (lane == 0) { sh_gv[wid] = gv; sh_gi[wid] = gi; sh_sv[wid] = sv; sh_si[wid] = si; }
    __syncthreads();

    if (wid == 0) {
        float v = sh_gv[lane]; int i = sh_gi[lane];
        float v2 = sh_sv[lane]; int i2 = sh_si[lane];
        #pragma unroll
        for (int off = 16; off; off >>= 1) {
            float wv = __shfl_xor_sync(0xffffffffu, v, off);
            int   wi = __shfl_xor_sync(0xffffffffu, i, off);
            if (wv > v || (wv == v && wi < i)) { v = wv; i = wi; }
            float wv2 = __shfl_xor_sync(0xffffffffu, v2, off);
            int   wi2 = __shfl_xor_sync(0xffffffffu, i2, off);
            if (wv2 > v2 || (wv2 == v2 && wi2 < i2)) { v2 = wv2; i2 = wi2; }
        }
        if (lane == 0) {
            fin_M = v * inv_t;            // row max of scaled = fl(max_l * inv_t)
            out[b] = (float)((t == 0.0f) ? i : i2);
        }
    }
    __syncthreads();

    // ---- pass 1.5: exp-sum; logits reread is L2-hot (74MB wave set) ----
    const float a  = inv_t * L2E;
    const float c0 = -fin_M * L2E;
    float acc0 = 0.0f, acc1 = 0.0f;
    for (int j = tid; j < NVEC; j += NT) {
        const float4 l4 = lrow[j];
        acc0 += ex2a(fmaf(l4.x, a, c0)) + ex2a(fmaf(l4.z, a, c0));
        acc1 += ex2a(fmaf(l4.y, a, c0)) + ex2a(fmaf(l4.w, a, c0));
    }
    float ssum = acc0 + acc1;
    #pragma unroll
    for (int off = 16; off; off >>= 1)
        ssum += __shfl_xor_sync(0xffffffffu, ssum, off);
    if (lane == 0) sh_sum[wid] = ssum;
    __syncthreads();
    if (wid == 0) {
        float c = sh_sum[lane];
        #pragma unroll
        for (int off = 16; off; off >>= 1)
            c += __shfl_xor_sync(0xffffffffu, c, off);
        if (lane == 0)
            fin_c = c0 - log2f(c);        // fold 1/sum into the exponent
    }
    __syncthreads();

    // ---- pass 2: probs = exp2(l*a + c), logits still L2-hot ----
    const float c = fin_c;
    for (int j = tid; j < NVEC; j += NT) {
        const float4 l4 = lrow[j];
        float4 p;
        p.x = ex2a(fmaf(l4.x, a, c));
        p.y = ex2a(fmaf(l4.y, a, c));
        p.z = ex2a(fmaf(l4.z, a, c));
        p.w = ex2a(fmaf(l4.w, a, c));
        __stcs(prow + j, p);              // streaming store
    }
}

extern "C" void kernel_launch(void* const* d_in, const int* in_sizes, int n_in,
                              void* d_out, int out_size) {
    const float* logits = (const float*)d_in[0];
    const float* temps  = (const float*)d_in[1];
    const float* noise  = (const float*)d_in[2];
    float* out = (float*)d_out;
    sampler_kernel<<<BB, NT>>>(logits, temps, noise, out);
}

// round 7
// speedup vs baseline: 1.5392x; 1.0177x over previous
#include <cuda_runtime.h>
#include <math_constants.h>

// Sampler: B=256 rows, V=128000 vocab.
// inputs: logits [B,V] f32, temperatures [B] f32, uniform_noise [B,V] f32
// output: [tokens (B floats)] ++ [probs (B*V floats)]

#define NT 1024
#define BB 256
#define VV 128000
#define NV8 (VV / 8)                  // 16000 float8 chunks per row (pass 1)
#define NV4 (VV / 4)                  // 32000 float4 chunks per row (pass 2)
#define L2E 1.4426950408889634f
#define LN2 0.6931471805599453f

__device__ __forceinline__ float lg2a(float x) {
    float r; asm("lg2.approx.f32 %0, %1;" : "=f"(r) : "f"(x)); return r;
}
__device__ __forceinline__ float ex2a(float x) {
    float r; asm("ex2.approx.f32 %0, %1;" : "=f"(r) : "f"(x)); return r;
}
// 32-byte logits load, pinned toward L2 retention for the pass-2 reread.
// (sm_103a ptxas requires .v8.b32/.v4.b64 with L2::evict_last)
__device__ __forceinline__ void ldg_el8(const float* p, float v[8]) {
    unsigned long long a0, a1, a2, a3;
    asm("ld.global.L2::evict_last.v4.b64 {%0,%1,%2,%3}, [%4];"
        : "=l"(a0), "=l"(a1), "=l"(a2), "=l"(a3) : "l"(p));
    v[0] = __uint_as_float((unsigned)(a0));       v[1] = __uint_as_float((unsigned)(a0 >> 32));
    v[2] = __uint_as_float((unsigned)(a1));       v[3] = __uint_as_float((unsigned)(a1 >> 32));
    v[4] = __uint_as_float((unsigned)(a2));       v[5] = __uint_as_float((unsigned)(a2 >> 32));
    v[6] = __uint_as_float((unsigned)(a3));       v[7] = __uint_as_float((unsigned)(a3 >> 32));
}
// 32-byte streaming noise load (single use)
__device__ __forceinline__ void ldcs8(const float* p, float v[8]) {
    float4 n0 = __ldcs((const float4*)p);
    float4 n1 = __ldcs((const float4*)p + 1);
    v[0] = n0.x; v[1] = n0.y; v[2] = n0.z; v[3] = n0.w;
    v[4] = n1.x; v[5] = n1.y; v[6] = n1.z; v[7] = n1.w;
}

__global__ void __launch_bounds__(NT)
sampler_kernel(const float* __restrict__ logits,
               const float* __restrict__ temps,
               const float* __restrict__ noise,
               float* __restrict__ out)
{
    const int b    = blockIdx.x;
    const int tid  = threadIdx.x;
    const int lane = tid & 31;
    const int wid  = tid >> 5;            // 0..31

    const float t      = temps[b];
    const float safe_t = (t == 0.0f) ? 1.0f : t;
    const float inv_t  = 1.0f / safe_t;
    const float a      = inv_t * L2E;     // logit -> log2-domain scale

    const float* __restrict__ lrow = logits + (size_t)b * VV;
    const float* __restrict__ nrow = noise  + (size_t)b * VV;
    float4* __restrict__ prow      = (float4*)(out + BB + (size_t)b * VV);

    // pass 1: greedy argmax + Gumbel argmax + online exp-sum (base = running gv)
    float gv = -CUDART_INF_F; int gi = 0;
    float sv = -CUDART_INF_F; int si = 0;
    float s  = 0.0f;          // sum of exp2((l - gv)*a), rebased when gv moves

    for (int j = tid; j < NV8; j += NT) {
        float lv[8], nv[8];
        ldg_el8(lrow + 8 * j, lv);
        ldcs8(nrow + 8 * j, nv);
        #pragma unroll
        for (int k = 0; k < 8; k++) {
            const int idx = 8 * j + k;
            const float l = lv[k];
            const float u = nv[k];
            // greedy argmax + online exp-sum share the branch
            if (l > gv) {
                s = s * ex2a((gv - l) * a) + 1.0f;    // rebase (exp2(-inf)=0 first time)
                gv = l; gi = idx;
            } else {
                s += ex2a((l - gv) * a);
            }
            // Gumbel: y = -log(u); fast LG2 + exact series fixup for u -> 1 tail
            float y = (-LN2) * lg2a(u);
            const float d = 1.0f - u;
            if (u > 0.99f)
                y = d * fmaf(d, fmaf(d, 0.33333333f, 0.5f), 1.0f);
            const float z = fmaf(lg2a(y), -LN2, l * inv_t);   // l/t + g
            if (z > sv) { sv = z; si = idx; }
        }
    }

    // ---- block reductions ----
    __shared__ float sh_gv[32]; __shared__ int sh_gi[32];
    __shared__ float sh_sv[32]; __shared__ int sh_si[32];
    __shared__ float sh_sum[32];
    __shared__ float fin_c;

    #pragma unroll
    for (int off = 16; off; off >>= 1) {
        float v  = __shfl_xor_sync(0xffffffffu, gv, off);
        int   i  = __shfl_xor_sync(0xffffffffu, gi, off);
        float ws = __shfl_xor_sync(0xffffffffu, s, off);
        if (v > gv) { s = fmaf(s, ex2a((gv - v) * a), ws); gv = v; gi = i; }
        else {
            s = fmaf(ws, ex2a((v - gv) * a), s);
            if (v == gv && i < gi) gi = i;
        }
        float v2 = __shfl_xor_sync(0xffffffffu, sv, off);
        int   i2 = __shfl_xor_sync(0xffffffffu, si, off);
        if (v2 > sv || (v2 == sv && i2 < si)) { sv = v2; si = i2; }
    }
    if (lane == 0) {
        sh_gv[wid] = gv; sh_gi[wid] = gi; sh_sum[wid] = s;
        sh_sv[wid] = sv; sh_si[wid] = si;
    }
    __syncthreads();

    if (wid == 0) {
        float v = sh_gv[lane]; int i = sh_gi[lane]; float c = sh_sum[lane];
        float v2 = sh_sv[lane]; int i2 = sh_si[lane];
        #pragma unroll
        for (int off = 16; off; off >>= 1) {
            float wv = __shfl_xor_sync(0xffffffffu, v, off);
            int   wi = __shfl_xor_sync(0xffffffffu, i, off);
            float wc = __shfl_xor_sync(0xffffffffu, c, off);
            if (wv > v) { c = fmaf(c, ex2a((v - wv) * a), wc); v = wv; i = wi; }
            else {
                c = fmaf(wc, ex2a((wv - v) * a), c);
                if (wv == v && wi < i) i = wi;
            }
            float wv2 = __shfl_xor_sync(0xffffffffu, v2, off);
            int   wi2 = __shfl_xor_sync(0xffffffffu, i2, off);
            if (wv2 > v2 || (wv2 == v2 && wi2 < i2)) { v2 = wv2; i2 = wi2; }
        }
        if (lane == 0) {
            // probs = exp2(l*a - max*a - log2(sum))
            fin_c = fmaf(-v, a, -log2f(c));
            out[b] = (float)((t == 0.0f) ? i : i2);
        }
    }
    __syncthreads();

    // ---- pass 2: probs = exp2(l*a + c); logits reread is L2-hot ----
    const float c = fin_c;
    const float4* __restrict__ lrow4 = (const float4*)lrow;
    for (int j = tid; j < NV4; j += NT) {
        const float4 l4 = lrow4[j];
        float4 p;
        p.x = ex2a(fmaf(l4.x, a, c));
        p.y = ex2a(fmaf(l4.y, a, c));
        p.z = ex2a(fmaf(l4.z, a, c));
        p.w = ex2a(fmaf(l4.w, a, c));
        __stcs(prow + j, p);              // streaming store
    }
}

extern "C" void kernel_launch(void* const* d_in, const int* in_sizes, int n_in,
                              void* d_out, int out_size) {
    const float* logits = (const float*)d_in[0];
    const float* temps  = (const float*)d_in[1];
    const float* noise  = (const float*)d_in[2];
    float* out = (float*)d_out;
    sampler_kernel<<<BB, NT>>>(logits, temps, noise, out);
}

// round 8
// speedup vs baseline: 1.6165x; 1.0502x over previous
#include <cuda_runtime.h>
#include <math_constants.h>

// Sampler: B=256 rows, V=128000 vocab.
// inputs: logits [B,V] f32, temperatures [B] f32, uniform_noise [B,V] f32
// output: [tokens (B floats)] ++ [probs (B*V floats)]

#define NT 1024
#define BB 256
#define VV 128000
#define NV8 (VV / 8)                  // 16000 float8 chunks per row (pass 1)
#define NV4 (VV / 4)                  // 32000 float4 chunks per row (pass 2)
#define L2E 1.4426950408889634f
#define LN2 0.6931471805599453f

__device__ __forceinline__ float lg2a(float x) {
    float r; asm("lg2.approx.f32 %0, %1;" : "=f"(r) : "f"(x)); return r;
}
__device__ __forceinline__ float ex2a(float x) {
    float r; asm("ex2.approx.f32 %0, %1;" : "=f"(r) : "f"(x)); return r;
}
// 32-byte logits load, pinned toward L2 retention for the pass-2 reread.
// (sm_103a ptxas requires .v8.b32/.v4.b64 with L2::evict_last)
__device__ __forceinline__ void ldg_el8(const float* p, float v[8]) {
    unsigned long long a0, a1, a2, a3;
    asm("ld.global.L2::evict_last.v4.b64 {%0,%1,%2,%3}, [%4];"
        : "=l"(a0), "=l"(a1), "=l"(a2), "=l"(a3) : "l"(p));
    v[0] = __uint_as_float((unsigned)(a0));  v[1] = __uint_as_float((unsigned)(a0 >> 32));
    v[2] = __uint_as_float((unsigned)(a1));  v[3] = __uint_as_float((unsigned)(a1 >> 32));
    v[4] = __uint_as_float((unsigned)(a2));  v[5] = __uint_as_float((unsigned)(a2 >> 32));
    v[6] = __uint_as_float((unsigned)(a3));  v[7] = __uint_as_float((unsigned)(a3 >> 32));
}

__global__ void __launch_bounds__(NT, 2)   // force <=32 regs -> 2 blocks/SM
sampler_kernel(const float* __restrict__ logits,
               const float* __restrict__ temps,
               const float* __restrict__ noise,
               float* __restrict__ out)
{
    const int b    = blockIdx.x;
    const int tid  = threadIdx.x;
    const int lane = tid & 31;
    const int wid  = tid >> 5;            // 0..31

    const float t      = temps[b];
    const float safe_t = (t == 0.0f) ? 1.0f : t;
    const float inv_t  = 1.0f / safe_t;
    const float a      = inv_t * L2E;     // logit -> log2-domain scale

    const float* __restrict__ lrow = logits + (size_t)b * VV;
    const float* __restrict__ nrow = noise  + (size_t)b * VV;
    float4* __restrict__ prow      = (float4*)(out + BB + (size_t)b * VV);

    // pass 1: greedy argmax + Gumbel argmax + online exp-sum (base = running gv)
    float gv = -CUDART_INF_F; int gi = 0;
    float sv = -CUDART_INF_F; int si = 0;
    float s  = 0.0f;          // sum of exp2((l - gv)*a), rebased when gv moves

    for (int j = tid; j < NV8; j += NT) {
        float lv[8];
        ldg_el8(lrow + 8 * j, lv);
        // consume in two 4-wide halves to keep live ranges small
        #pragma unroll
        for (int h = 0; h < 2; h++) {
            const float4 n4 = __ldcs((const float4*)(nrow + 8 * j) + h);
            const float nv[4] = {n4.x, n4.y, n4.z, n4.w};
            #pragma unroll
            for (int k = 0; k < 4; k++) {
                const int idx = 8 * j + 4 * h + k;
                const float l = lv[4 * h + k];
                const float u = nv[k];
                // greedy argmax + online exp-sum share the branch
                if (l > gv) {
                    s = s * ex2a((gv - l) * a) + 1.0f;  // rebase (exp2(-inf)=0 first time)
                    gv = l; gi = idx;
                } else {
                    s += ex2a((l - gv) * a);
                }
                // Gumbel: y = -log(u); fast LG2 + exact series fixup for u -> 1 tail
                float y = (-LN2) * lg2a(u);
                const float d = 1.0f - u;
                if (u > 0.99f)
                    y = d * fmaf(d, fmaf(d, 0.33333333f, 0.5f), 1.0f);
                const float z = fmaf(lg2a(y), -LN2, l * inv_t);   // l/t + g
                if (z > sv) { sv = z; si = idx; }
            }
        }
    }

    // ---- block reductions ----
    __shared__ float sh_gv[32]; __shared__ int sh_gi[32];
    __shared__ float sh_sv[32]; __shared__ int sh_si[32];
    __shared__ float sh_sum[32];
    __shared__ float fin_c;

    #pragma unroll
    for (int off = 16; off; off >>= 1) {
        float v  = __shfl_xor_sync(0xffffffffu, gv, off);
        int   i  = __shfl_xor_sync(0xffffffffu, gi, off);
        float ws = __shfl_xor_sync(0xffffffffu, s, off);
        if (v > gv) { s = fmaf(s, ex2a((gv - v) * a), ws); gv = v; gi = i; }
        else {
            s = fmaf(ws, ex2a((v - gv) * a), s);
            if (v == gv && i < gi) gi = i;
        }
        float v2 = __shfl_xor_sync(0xffffffffu, sv, off);
        int   i2 = __shfl_xor_sync(0xffffffffu, si, off);
        if (v2 > sv || (v2 == sv && i2 < si)) { sv = v2; si = i2; }
    }
    if (lane == 0) {
        sh_gv[wid] = gv; sh_gi[wid] = gi; sh_sum[wid] = s;
        sh_sv[wid] = sv; sh_si[wid] = si;
    }
    __syncthreads();

    if (wid == 0) {
        float v = sh_gv[lane]; int i = sh_gi[lane]; float c = sh_sum[lane];
        float v2 = sh_sv[lane]; int i2 = sh_si[lane];
        #pragma unroll
        for (int off = 16; off; off >>= 1) {
            float wv = __shfl_xor_sync(0xffffffffu, v, off);
            int   wi = __shfl_xor_sync(0xffffffffu, i, off);
            float wc = __shfl_xor_sync(0xffffffffu, c, off);
            if (wv > v) { c = fmaf(c, ex2a((v - wv) * a), wc); v = wv; i = wi; }
            else {
                c = fmaf(wc, ex2a((wv - v) * a), c);
                if (wv == v && wi < i) i = wi;
            }
            float wv2 = __shfl_xor_sync(0xffffffffu, v2, off);
            int   wi2 = __shfl_xor_sync(0xffffffffu, i2, off);
            if (wv2 > v2 || (wv2 == v2 && wi2 < i2)) { v2 = wv2; i2 = wi2; }
        }
        if (lane == 0) {
            // probs = exp2(l*a - max*a - log2(sum))
            fin_c = fmaf(-v, a, -log2f(c));
            out[b] = (float)((t == 0.0f) ? i : i2);
        }
    }
    __syncthreads();

    // ---- pass 2: probs = exp2(l*a + c); logits reread is L2-hot ----
    const float c = fin_c;
    const float4* __restrict__ lrow4 = (const float4*)lrow;
    for (int j = tid; j < NV4; j += NT) {
        const float4 l4 = lrow4[j];
        float4 p;
        p.x = ex2a(fmaf(l4.x, a, c));
        p.y = ex2a(fmaf(l4.y, a, c));
        p.z = ex2a(fmaf(l4.z, a, c));
        p.w = ex2a(fmaf(l4.w, a, c));
        __stcs(prow + j, p);              // streaming store
    }
}

extern "C" void kernel_launch(void* const* d_in, const int* in_sizes, int n_in,
                              void* d_out, int out_size) {
    const float* logits = (const float*)d_in[0];
    const float* temps  = (const float*)d_in[1];
    const float* noise  = (const float*)d_in[2];
    float* out = (float*)d_out;
    sampler_kernel<<<BB, NT>>>(logits, temps, noise, out);
}

// round 9
// speedup vs baseline: 1.8362x; 1.1359x over previous
#include <cuda_runtime.h>
#include <math_constants.h>

// Sampler: B=256 rows, V=128000 vocab.
// inputs: logits [B,V] f32, temperatures [B] f32, uniform_noise [B,V] f32
// output: [tokens (B floats)] ++ [probs (B*V floats)]

#define NT 1024
#define BB 256
#define VV 128000
#define NV8 (VV / 8)                  // 16000 float8 chunks per row (pass 1)
#define NV4 (VV / 4)                  // 32000 float4 chunks per row (pass 2)
#define L2E 1.4426950408889634f
#define LN2 0.6931471805599453f

__device__ __forceinline__ float lg2a(float x) {
    float r; asm("lg2.approx.f32 %0, %1;" : "=f"(r) : "f"(x)); return r;
}
__device__ __forceinline__ float ex2a(float x) {
    float r; asm("ex2.approx.f32 %0, %1;" : "=f"(r) : "f"(x)); return r;
}
// 32-byte logits load, pinned toward L2 retention for the pass-2 reread.
// (sm_103a ptxas requires .v8.b32/.v4.b64 with L2::evict_last)
__device__ __forceinline__ void ldg_el8(const float* p, float v[8]) {
    unsigned long long a0, a1, a2, a3;
    asm("ld.global.L2::evict_last.v4.b64 {%0,%1,%2,%3}, [%4];"
        : "=l"(a0), "=l"(a1), "=l"(a2), "=l"(a3) : "l"(p));
    v[0] = __uint_as_float((unsigned)(a0));  v[1] = __uint_as_float((unsigned)(a0 >> 32));
    v[2] = __uint_as_float((unsigned)(a1));  v[3] = __uint_as_float((unsigned)(a1 >> 32));
    v[4] = __uint_as_float((unsigned)(a2));  v[5] = __uint_as_float((unsigned)(a2 >> 32));
    v[6] = __uint_as_float((unsigned)(a3));  v[7] = __uint_as_float((unsigned)(a3 >> 32));
}

__global__ void __launch_bounds__(NT, 2)   // cap regs at 32 -> 2 blocks/SM
sampler_kernel(const float* __restrict__ logits,
               const float* __restrict__ temps,
               const float* __restrict__ noise,
               float* __restrict__ out)
{
    const int b    = blockIdx.x;
    const int tid  = threadIdx.x;
    const int lane = tid & 31;
    const int wid  = tid >> 5;            // 0..31

    const float t      = temps[b];
    const float safe_t = (t == 0.0f) ? 1.0f : t;
    const float inv_t  = 1.0f / safe_t;
    const float a      = inv_t * L2E;     // logit -> log2-domain scale

    const float* __restrict__ lrow = logits + (size_t)b * VV;
    const float* __restrict__ nrow = noise  + (size_t)b * VV;
    float4* __restrict__ prow      = (float4*)(out + BB + (size_t)b * VV);

    // pass 1: greedy argmax + Gumbel argmax + online exp-sum (base = running gv)
    float gv = -CUDART_INF_F; int gi = 0;
    float sv = -CUDART_INF_F; int si = 0;
    float s  = 0.0f;          // sum of exp2((l - gv)*a), rebased when gv moves

    for (int j = tid; j < NV8; j += NT) {
        float lv[8];
        ldg_el8(lrow + 8 * j, lv);
        // consume in two 4-wide halves to keep live ranges small
        #pragma unroll
        for (int h = 0; h < 2; h++) {
            const float4 n4 = __ldcs((const float4*)(nrow + 8 * j) + h);
            const float nv[4] = {n4.x, n4.y, n4.z, n4.w};
            #pragma unroll
            for (int k = 0; k < 4; k++) {
                const int idx = 8 * j + 4 * h + k;
                const float l = lv[4 * h + k];
                const float u = nv[k];
                // greedy argmax + online exp-sum share the branch
                if (l > gv) {
                    s = s * ex2a((gv - l) * a) + 1.0f;  // rebase (exp2(-inf)=0 first time)
                    gv = l; gi = idx;
                } else {
                    s += ex2a((l - gv) * a);
                }
                // Gumbel: y = -log(u); fast LG2 + exact series fixup for u -> 1 tail
                float y = (-LN2) * lg2a(u);
                const float d = 1.0f - u;
                if (u > 0.99f)
                    y = d * fmaf(d, fmaf(d, 0.33333333f, 0.5f), 1.0f);
                const float z = fmaf(lg2a(y), -LN2, l * inv_t);   // l/t + g
                if (z > sv) { sv = z; si = idx; }
            }
        }
    }

    // ---- block reductions ----
    __shared__ float sh_gv[32]; __shared__ int sh_gi[32];
    __shared__ float sh_sv[32]; __shared__ int sh_si[32];
    __shared__ float sh_sum[32];
    __shared__ float fin_c;

    #pragma unroll
    for (int off = 16; off; off >>= 1) {
        float v  = __shfl_xor_sync(0xffffffffu, gv, off);
        int   i  = __shfl_xor_sync(0xffffffffu, gi, off);
        float ws = __shfl_xor_sync(0xffffffffu, s, off);
        if (v > gv) { s = fmaf(s, ex2a((gv - v) * a), ws); gv = v; gi = i; }
        else {
            s = fmaf(ws, ex2a((v - gv) * a), s);
            if (v == gv && i < gi) gi = i;
        }
        float v2 = __shfl_xor_sync(0xffffffffu, sv, off);
        int   i2 = __shfl_xor_sync(0xffffffffu, si, off);
        if (v2 > sv || (v2 == sv && i2 < si)) { sv = v2; si = i2; }
    }
    if (lane == 0) {
        sh_gv[wid] = gv; sh_gi[wid] = gi; sh_sum[wid] = s;
        sh_sv[wid] = sv; sh_si[wid] = si;
    }
    __syncthreads();

    if (wid == 0) {
        float v = sh_gv[lane]; int i = sh_gi[lane]; float c = sh_sum[lane];
        float v2 = sh_sv[lane]; int i2 = sh_si[lane];
        #pragma unroll
        for (int off = 16; off; off >>= 1) {
            float wv = __shfl_xor_sync(0xffffffffu, v, off);
            int   wi = __shfl_xor_sync(0xffffffffu, i, off);
            float wc = __shfl_xor_sync(0xffffffffu, c, off);
            if (wv > v) { c = fmaf(c, ex2a((v - wv) * a), wc); v = wv; i = wi; }
            else {
                c = fmaf(wc, ex2a((wv - v) * a), c);
                if (wv == v && wi < i) i = wi;
            }
            float wv2 = __shfl_xor_sync(0xffffffffu, v2, off);
            int   wi2 = __shfl_xor_sync(0xffffffffu, i2, off);
            if (wv2 > v2 || (wv2 == v2 && wi2 < i2)) { v2 = wv2; i2 = wi2; }
        }
        if (lane == 0) {
            // probs = exp2(l*a - max*a - log2(sum))
            fin_c = fmaf(-v, a, -log2f(c));
            out[b] = (float)((t == 0.0f) ? i : i2);
        }
    }
    __syncthreads();

    // ---- pass 2: probs = exp2(l*a + c) ----
    // REVERSE order (LIFO): the row tail is the freshest L2 content after
    // pass 1; consuming most-recent-first maximizes hits under LRU.
    // Unrolled x2 for per-thread MLP in the load->EX2->store chain.
    const float c = fin_c;
    const float4* __restrict__ lrow4 = (const float4*)lrow;
    int j = NV4 - NT + tid;               // top chunk for this thread
    for (; j >= NT; j -= 2 * NT) {
        const float4 la = lrow4[j];
        const float4 lb = lrow4[j - NT];
        float4 pa, pb;
        pa.x = ex2a(fmaf(la.x, a, c)); pa.y = ex2a(fmaf(la.y, a, c));
        pa.z = ex2a(fmaf(la.z, a, c)); pa.w = ex2a(fmaf(la.w, a, c));
        pb.x = ex2a(fmaf(lb.x, a, c)); pb.y = ex2a(fmaf(lb.y, a, c));
        pb.z = ex2a(fmaf(lb.z, a, c)); pb.w = ex2a(fmaf(lb.w, a, c));
        __stcs(prow + j, pa);
        __stcs(prow + (j - NT), pb);
    }
    if (j >= 0) {
        const float4 la = lrow4[j];
        float4 pa;
        pa.x = ex2a(fmaf(la.x, a, c)); pa.y = ex2a(fmaf(la.y, a, c));
        pa.z = ex2a(fmaf(la.z, a, c)); pa.w = ex2a(fmaf(la.w, a, c));
        __stcs(prow + j, pa);
    }
}

extern "C" void kernel_launch(void* const* d_in, const int* in_sizes, int n_in,
                              void* d_out, int out_size) {
    const float* logits = (const float*)d_in[0];
    const float* temps  = (const float*)d_in[1];
    const float* noise  = (const float*)d_in[2];
    float* out = (float*)d_out;
    sampler_kernel<<<BB, NT>>>(logits, temps, noise, out);
}